// round 8
// baseline (speedup 1.0000x reference)
#include <cuda_runtime.h>
#include <math.h>

// ---------------------------------------------------------------------------
// SeFT network, round 6:
//  - gather: coalesced ballot compaction (k_rows + k_compact)
//  - k_mlp: smem-staged weights with register prefetch pipeline, f32x2 FFMA
//  - attention fully parallelized over l-chunks:
//      k_score (B x 8 blocks)  -> scores + per-chunk per-head max
//      k_expsum (B*H blocks)   -> exp weights + 1/sum
//      k_wsum  (B x 8 blocks)  -> partial weighted enc sums
//      k_final (B blocks)      -> combine partials
// ---------------------------------------------------------------------------

#define BMAX    32
#define LSTRIDE 2048
#define NCHUNK  8           // LSTRIDE / 256
#define HID     128
#define NIN     34
#define ASTR    36          // activation row stride (floats)

typedef unsigned long long ull;

__device__ float    g_St[BMAX * LSTRIDE];
__device__ float    g_Sc[BMAX * LSTRIDE];
__device__ float    g_Sx[BMAX * LSTRIDE];
__device__ int      g_lens[BMAX];
__device__ int      g_maxlen;
__device__ int      g_rowcnt[4096];
__device__ unsigned g_rowmask[4096];
__device__ float    g_rowtime[4096];
__device__ float    g_enc[(size_t)BMAX * LSTRIDE * HID];   // [b][l][e]
__device__ float    g_kT [(size_t)BMAX * HID * LSTRIDE];   // [b][e][l]
__device__ float    g_q  [BMAX * HID];
__device__ float    g_scs[(size_t)BMAX * 4 * LSTRIDE];     // [b][h][l] scores
__device__ float    g_w  [(size_t)BMAX * 4 * LSTRIDE];     // [b][h][l] exp weights
__device__ float    g_bmax[BMAX * 4 * NCHUNK];             // [(b*4+h)*8+chunk]
__device__ float    g_inv [BMAX * 4];                      // 1/sum per (b,h)
__device__ float    g_part[(size_t)BMAX * NCHUNK * 512];   // [b][chunk][h*128+e]

// ---- packed fp32x2 helpers -------------------------------------------------
__device__ __forceinline__ ull pack2(float x, float y) {
    ull r;
    asm("mov.b64 %0, {%1, %2};" : "=l"(r) : "f"(x), "f"(y));
    return r;
}
__device__ __forceinline__ void unpack2(ull v, float& lo, float& hi) {
    asm("mov.b64 {%0, %1}, %2;" : "=f"(lo), "=f"(hi) : "l"(v));
}
__device__ __forceinline__ ull ffma2(ull a, ull b, ull c) {
    ull d;
    asm("fma.rn.f32x2 %0, %1, %2, %3;" : "=l"(d) : "l"(a), "l"(b), "l"(c));
    return d;
}

// ---------------------------------------------------------------------------
// Kernel 1: per-row nonzero mask/count/time. One warp per row, coalesced.
// ---------------------------------------------------------------------------
__global__ void k_rows(const float* __restrict__ times,
                       const int*   __restrict__ time_ptr,
                       const int*   __restrict__ M,
                       int R, int V, int n_times)
{
    int w = (blockIdx.x * blockDim.x + threadIdx.x) >> 5;
    int lane = threadIdx.x & 31;
    if (w >= R) return;
    int m = 0;
    if (lane < V) m = (M[w * V + lane] != 0);
    unsigned mask = __ballot_sync(0xffffffffu, m);
    if (lane == 0) {
        g_rowmask[w] = mask;
        g_rowcnt[w]  = __popc(mask);
        int lo = 0, hi = n_times - 1;
        while (lo < hi) {
            int mid = (lo + hi + 1) >> 1;
            if (time_ptr[mid] <= w) lo = mid; else hi = mid - 1;
        }
        g_rowtime[w] = times[lo];
    }
}

// ---------------------------------------------------------------------------
// Kernel 2: per-patient compaction (rows contiguous per patient).
// ---------------------------------------------------------------------------
__global__ void k_compact(const float* __restrict__ X, int R, int V, int B)
{
    int b = blockIdx.x;
    int rpp = R / B;
    int r0 = b * rpp;
    int t = threadIdx.x;

    __shared__ int ssum[256];
    __shared__ int sstart[256];
    int cnt = (t < rpp) ? g_rowcnt[r0 + t] : 0;
    ssum[t] = cnt;
    __syncthreads();
    for (int off = 1; off < 256; off <<= 1) {
        int v = (t >= off) ? ssum[t - off] : 0;
        __syncthreads();
        ssum[t] += v;
        __syncthreads();
    }
    int tot = ssum[255];
    sstart[t] = ssum[t] - cnt;
    __syncthreads();

    int lane = t & 31, w = t >> 5;
    for (int lr = w; lr < rpp; lr += 8) {
        int r = r0 + lr;
        unsigned mask = g_rowmask[r];
        float tv = g_rowtime[r];
        int start = sstart[lr];
        if (lane < V && ((mask >> lane) & 1u)) {
            int pos = start + __popc(mask & ((1u << lane) - 1u));
            if (pos < LSTRIDE) {
                g_St[b * LSTRIDE + pos] = tv;
                g_Sc[b * LSTRIDE + pos] = (float)lane;
                g_Sx[b * LSTRIDE + pos] = X[r * V + lane];
            }
        }
    }
    if (t == 0) {
        int L = min(tot, LSTRIDE);
        g_lens[b] = L;
        atomicMax(&g_maxlen, L);   // idempotent across replays
    }
}

// ---------------------------------------------------------------------------
// 128->128 dense layer, f32x2, pipelined smem weight staging.
// Thread (r = t&63, h = t>>6) computes output rows r, r+64 over 16 obs.
// wbuf layout wbuf[kk*129 + o]: conflict-free STS and LDS.
// Next chunk is prefetched into registers while current chunk computes.
// ---------------------------------------------------------------------------
__device__ __forceinline__ void dense128(const float* __restrict__ W,
                                         const float* __restrict__ bias,
                                         const float* sIn, float* wbuf,
                                         ull accA[8], ull accB[8],
                                         int r, int h, int tid)
{
    float bA = __ldg(&bias[r]);
    float bB = __ldg(&bias[r + 64]);
    ull iA = pack2(bA, bA), iB = pack2(bB, bB);
#pragma unroll
    for (int j = 0; j < 8; j++) { accA[j] = iA; accB[j] = iB; }

    // prefetch chunk 0 into registers: thread handles i4 = tid + j*128
    float4 pf[8];
#pragma unroll
    for (int j = 0; j < 8; j++) {
        int i4 = tid + j * 128;
        int o  = i4 >> 3;             // (i4*4)/32
        int kk = (i4 << 2) & 31;
        pf[j] = __ldg((const float4*)(W + o * HID + 0 * 32 + kk));
    }

    for (int c = 0; c < 4; c++) {
        __syncthreads();              // previous use of wbuf done
#pragma unroll
        for (int j = 0; j < 8; j++) {
            int i4 = tid + j * 128;
            int o  = i4 >> 3;
            int kk = (i4 << 2) & 31;
            wbuf[kk * 129 + o]       = pf[j].x;
            wbuf[(kk + 1) * 129 + o] = pf[j].y;
            wbuf[(kk + 2) * 129 + o] = pf[j].z;
            wbuf[(kk + 3) * 129 + o] = pf[j].w;
        }
        __syncthreads();
        if (c < 3) {
#pragma unroll
            for (int j = 0; j < 8; j++) {
                int i4 = tid + j * 128;
                int o  = i4 >> 3;
                int kk = (i4 << 2) & 31;
                pf[j] = __ldg((const float4*)(W + o * HID + (c + 1) * 32 + kk));
            }
        }
#pragma unroll 4
        for (int kk = 0; kk < 32; kk++) {
            float wA = wbuf[kk * 129 + r];
            float wB = wbuf[kk * 129 + 64 + r];
            ull wA2 = pack2(wA, wA), wB2 = pack2(wB, wB);
            const ulonglong2* row =
                (const ulonglong2*)(sIn + (c * 32 + kk) * ASTR + h * 16);
#pragma unroll
            for (int p = 0; p < 4; p++) {
                ulonglong2 v = row[p];
                accA[2 * p]     = ffma2(v.x, wA2, accA[2 * p]);
                accA[2 * p + 1] = ffma2(v.y, wA2, accA[2 * p + 1]);
                accB[2 * p]     = ffma2(v.x, wB2, accB[2 * p]);
                accB[2 * p + 1] = ffma2(v.y, wB2, accB[2 * p + 1]);
            }
        }
    }
    __syncthreads();                  // all compute done before wbuf reuse
}

// relu epilogue into [k][obs] smem for rows r, r+64, obs half h
__device__ __forceinline__ void epi_relu(float* dst, ull accA[8], ull accB[8],
                                         int r, int h)
{
    float* dA = dst + r * ASTR + h * 16;
    float* dB = dst + (r + 64) * ASTR + h * 16;
#pragma unroll
    for (int j = 0; j < 8; j++) {
        float lo, hi;
        unpack2(accA[j], lo, hi);
        *(ull*)(dA + 2 * j) = pack2(fmaxf(lo, 0.f), fmaxf(hi, 0.f));
        unpack2(accB[j], lo, hi);
        *(ull*)(dB + 2 * j) = pack2(fmaxf(lo, 0.f), fmaxf(hi, 0.f));
    }
}

// ---------------------------------------------------------------------------
// Kernel 3: fused MLP + projection, 32-obs tiles.
// Block 0 = query path (lastfeat inline, Wq -> g_q). Others: enc + kT.
//   L0: in sf, w sA, out sA      L1: in sA, w sB, out sB
//   L2: in sB, w sA, out sA+enc  Pr: in sA, w sB, out global
// ---------------------------------------------------------------------------
__global__ __launch_bounds__(128) void k_mlp(
    const float* __restrict__ W0, const float* __restrict__ b0,
    const float* __restrict__ W1, const float* __restrict__ b1,
    const float* __restrict__ W2, const float* __restrict__ b2,
    const float* __restrict__ Wk, const float* __restrict__ bk,
    const float* __restrict__ Wq, const float* __restrict__ bq,
    int B)
{
    __shared__ __align__(16) float sf[NIN * ASTR];
    __shared__ __align__(16) float sA[HID * ASTR];
    __shared__ __align__(16) float sB[HID * ASTR];

    int tid = threadIdx.x;
    int r = tid & 63;
    int h = tid >> 6;

    bool special = (blockIdx.x == 0);
    int b = 0, l0 = 0, nv = 0;
    if (!special) {
        int bi = blockIdx.x - 1;
        b = bi >> 6;
        int lt = bi & 63;
        int len = g_lens[b];
        l0 = lt * 32;
        if (l0 >= len) return;
        nv = min(32, len - l0);
    } else {
        nv = min(B, 32);
    }

    // stage W0 [128][34] into sA at stride 129 (dead until L0 epilogue)
    for (int i = tid; i < HID * NIN; i += 128) {
        int o = i / NIN, k = i - o * NIN;
        sA[k * 129 + o] = __ldg(&W0[i]);
    }

    // features into [k][obs] layout
    if (tid < 32) {
        int o = tid;
        float tv = 0.f, cv = 0.f, xv = 0.f;
        if (special) {
            int L = g_maxlen;
            if (o < nv && L >= 1 && g_lens[o] == L) {
                tv = g_St[o * LSTRIDE + L - 1];
                cv = g_Sc[o * LSTRIDE + L - 1];
                xv = g_Sx[o * LSTRIDE + L - 1];
            }
        } else if (o < nv) {
            tv = g_St[b * LSTRIDE + l0 + o];
            cv = g_Sc[b * LSTRIDE + l0 + o];
            xv = g_Sx[b * LSTRIDE + l0 + o];
        }
#pragma unroll
        for (int i = 0; i < 16; i++) {
            float ts = powf(100.0f, (float)i * (1.0f / 15.0f));
            float sn, cs;
            sincosf(tv / ts, &sn, &cs);
            sf[i * ASTR + o]        = sn;
            sf[(16 + i) * ASTR + o] = cs;
        }
        sf[32 * ASTR + o] = cv;
        sf[33 * ASTR + o] = xv;
    }
    __syncthreads();

    ull accA[8], accB[8];

    // ---- layer 0: 34 -> 128, relu (weights in sA, input sf) ----
    {
        float bA = __ldg(&b0[r]);
        float bB = __ldg(&b0[r + 64]);
        ull iA = pack2(bA, bA), iB = pack2(bB, bB);
#pragma unroll
        for (int j = 0; j < 8; j++) { accA[j] = iA; accB[j] = iB; }
#pragma unroll 2
        for (int k = 0; k < NIN; k++) {
            float wA = sA[k * 129 + r];
            float wB = sA[k * 129 + 64 + r];
            ull wA2 = pack2(wA, wA), wB2 = pack2(wB, wB);
            const ulonglong2* row = (const ulonglong2*)(sf + k * ASTR + h * 16);
#pragma unroll
            for (int p = 0; p < 4; p++) {
                ulonglong2 v = row[p];
                accA[2 * p]     = ffma2(v.x, wA2, accA[2 * p]);
                accA[2 * p + 1] = ffma2(v.y, wA2, accA[2 * p + 1]);
                accB[2 * p]     = ffma2(v.x, wB2, accB[2 * p]);
                accB[2 * p + 1] = ffma2(v.y, wB2, accB[2 * p + 1]);
            }
        }
        __syncthreads();            // weights in sA dead after this
        epi_relu(sA, accA, accB, r, h);
    }
    __syncthreads();

    // ---- layer 1: 128 -> 128, relu (in sA, weights+out sB) ----
    dense128(W1, b1, sA, sB, accA, accB, r, h, tid);
    epi_relu(sB, accA, accB, r, h);
    __syncthreads();

    // ---- layer 2 (enc): 128 -> 128, linear (in sB, weights+out sA) ----
    dense128(W2, b2, sB, sA, accA, accB, r, h, tid);
    {
        float vA[16], vB[16];
#pragma unroll
        for (int j = 0; j < 8; j++) {
            unpack2(accA[j], vA[2 * j], vA[2 * j + 1]);
            unpack2(accB[j], vB[2 * j], vB[2 * j + 1]);
        }
        float* dA = sA + r * ASTR + h * 16;
        float* dB = sA + (r + 64) * ASTR + h * 16;
#pragma unroll
        for (int j = 0; j < 8; j++) {
            *(ull*)(dA + 2 * j) = accA[j];
            *(ull*)(dB + 2 * j) = accB[j];
        }
        if (!special) {
#pragma unroll
            for (int o = 0; o < 16; o++) {
                int og = h * 16 + o;
                if (og < nv) {
                    size_t base = ((size_t)b * LSTRIDE + l0 + og) * HID;
                    g_enc[base + r]      = vA[o];
                    g_enc[base + 64 + r] = vB[o];
                }
            }
        }
    }
    __syncthreads();

    // ---- projection: Wk (normal) or Wq (special); in sA, weights sB ----
    dense128(special ? Wq : Wk, special ? bq : bk, sA, sB, accA, accB, r, h, tid);
    {
        float vA[16], vB[16];
#pragma unroll
        for (int j = 0; j < 8; j++) {
            unpack2(accA[j], vA[2 * j], vA[2 * j + 1]);
            unpack2(accB[j], vB[2 * j], vB[2 * j + 1]);
        }
        if (special) {
#pragma unroll
            for (int o = 0; o < 16; o++) {
                int og = h * 16 + o;
                if (og < nv) {
                    g_q[og * HID + r]      = vA[o];
                    g_q[og * HID + 64 + r] = vB[o];
                }
            }
        } else {
            float* gkA = g_kT + ((size_t)b * HID + r) * LSTRIDE + l0 + h * 16;
            float* gkB = g_kT + ((size_t)b * HID + 64 + r) * LSTRIDE + l0 + h * 16;
#pragma unroll
            for (int o = 0; o < 16; o += 4) {
                int og = h * 16 + o;
                if (og + 4 <= nv) {
                    *(float4*)(gkA + o) = make_float4(vA[o], vA[o+1], vA[o+2], vA[o+3]);
                    *(float4*)(gkB + o) = make_float4(vB[o], vB[o+1], vB[o+2], vB[o+3]);
                } else {
                    for (int m = 0; m < 4; m++)
                        if (og + m < nv) { gkA[o + m] = vA[o + m]; gkB[o + m] = vB[o + m]; }
                }
            }
        }
    }
}

// ---------------------------------------------------------------------------
// Kernel 4: scores per l-chunk. grid (B, NCHUNK), 256 threads.
// Thread t owns l = chunk*256 + t; coalesced over l for every e.
// Writes g_scs and per-(chunk,h) block max.
// ---------------------------------------------------------------------------
__global__ __launch_bounds__(256) void k_score()
{
    int b     = blockIdx.x;
    int chunk = blockIdx.y;
    int t     = threadIdx.x;
    int len   = min(g_lens[b], LSTRIDE);
    int l     = chunk * 256 + t;

    __shared__ float sq[HID];
    __shared__ __align__(16) float4 sred[256];

    if (t < HID) sq[t] = g_q[b * HID + t];
    __syncthreads();

    const float scale = 0.17677669529663687f; // 1/sqrt(32)
    float a0 = -1e30f, a1 = -1e30f, a2 = -1e30f, a3 = -1e30f;

    if (l < len) {
        const float* kb = g_kT + (size_t)b * HID * LSTRIDE + l;
        float s[4];
#pragma unroll
        for (int h = 0; h < 4; h++) {
            float acc = 0.f;
#pragma unroll 8
            for (int e2 = 0; e2 < 32; e2++)
                acc = fmaf(__ldg(&kb[(size_t)(h * 32 + e2) * LSTRIDE]), sq[h * 32 + e2], acc);
            s[h] = acc * scale;
            g_scs[((size_t)b * 4 + h) * LSTRIDE + l] = s[h];
        }
        a0 = s[0]; a1 = s[1]; a2 = s[2]; a3 = s[3];
    }

    sred[t] = make_float4(a0, a1, a2, a3);
    __syncthreads();
    for (int s = 128; s > 0; s >>= 1) {
        if (t < s) {
            float4 x = sred[t], y = sred[t + s];
            sred[t] = make_float4(fmaxf(x.x, y.x), fmaxf(x.y, y.y),
                                  fmaxf(x.z, y.z), fmaxf(x.w, y.w));
        }
        __syncthreads();
    }
    if (t < 4) {
        float v = (t == 0) ? sred[0].x : (t == 1) ? sred[0].y
                : (t == 2) ? sred[0].z : sred[0].w;
        g_bmax[(b * 4 + t) * NCHUNK + chunk] = v;
    }
}

// ---------------------------------------------------------------------------
// Kernel 5: exp weights + 1/sum per (b,h). grid B*4, 256 threads.
// Pads g_w with zeros up to LSTRIDE.
// ---------------------------------------------------------------------------
__global__ __launch_bounds__(256) void k_expsum()
{
    int bh = blockIdx.x;
    int b  = bh >> 2;
    int t  = threadIdx.x;
    int len = min(g_lens[b], LSTRIDE);

    __shared__ float sred[256];

    float mx = -1e30f;
#pragma unroll
    for (int c = 0; c < NCHUNK; c++) mx = fmaxf(mx, g_bmax[bh * NCHUNK + c]);

    const float* scr = g_scs + (size_t)bh * LSTRIDE;
    float* wr = g_w + (size_t)bh * LSTRIDE;

    float lsm = 0.f;
    for (int l = t; l < LSTRIDE; l += 256) {
        float e = 0.f;
        if (l < len) { e = expf(__ldg(&scr[l]) - mx); }
        wr[l] = e;
        lsm += e;
    }
    sred[t] = lsm;
    __syncthreads();
    for (int s = 128; s > 0; s >>= 1) {
        if (t < s) sred[t] += sred[t + s];
        __syncthreads();
    }
    if (t == 0) g_inv[bh] = (len > 0) ? (1.f / sred[0]) : 0.f;
}

// ---------------------------------------------------------------------------
// Kernel 6: partial weighted enc sums per l-chunk. grid (B, NCHUNK), 512 thr.
// Thread (h = t>>7, e = t&127). enc read coalesced; w chunk staged in smem.
// ---------------------------------------------------------------------------
__global__ __launch_bounds__(512) void k_wsum()
{
    int b     = blockIdx.x;
    int chunk = blockIdx.y;
    int t     = threadIdx.x;
    int len   = min(g_lens[b], LSTRIDE);
    int l0    = chunk * 256;
    float* part = g_part + ((size_t)b * NCHUNK + chunk) * 512;

    if (l0 >= len) { part[t] = 0.f; return; }
    int nl = min(256, len - l0);

    __shared__ float sw[4 * 256];
    for (int i = t; i < 4 * 256; i += 512) {
        int hh = i >> 8, li = i & 255;
        sw[i] = g_w[((size_t)b * 4 + hh) * LSTRIDE + l0 + li];
    }
    __syncthreads();

    int h = t >> 7;
    int e = t & 127;
    const float* encb = g_enc + ((size_t)b * LSTRIDE + l0) * HID + e;
    const float* swh = sw + h * 256;

    float a0 = 0.f, a1 = 0.f;
    int l = 0;
    for (; l + 1 < nl; l += 2) {
        a0 = fmaf(swh[l],     __ldg(&encb[(size_t)l * HID]),       a0);
        a1 = fmaf(swh[l + 1], __ldg(&encb[(size_t)(l + 1) * HID]), a1);
    }
    if (l < nl) a0 = fmaf(swh[l], __ldg(&encb[(size_t)l * HID]), a0);
    part[t] = a0 + a1;
}

// ---------------------------------------------------------------------------
// Kernel 7: combine partials. grid B, 512 threads. out[b][h*128+e].
// ---------------------------------------------------------------------------
__global__ __launch_bounds__(512) void k_final(float* __restrict__ out)
{
    int b = blockIdx.x;
    int t = threadIdx.x;
    int h = t >> 7;
    const float* part = g_part + (size_t)b * NCHUNK * 512;
    float a = 0.f;
#pragma unroll
    for (int c = 0; c < NCHUNK; c++) a += part[c * 512 + t];
    out[b * 512 + t] = a * g_inv[b * 4 + h];
}

// ---------------------------------------------------------------------------
extern "C" void kernel_launch(void* const* d_in, const int* in_sizes, int n_in,
                              void* d_out, int out_size)
{
    const float* times    = (const float*)d_in[0];
    const int*   time_ptr = (const int*)  d_in[1];
    const float* X        = (const float*)d_in[2];
    const int*   M        = (const int*)  d_in[3];
    const float* W0 = (const float*)d_in[6];
    const float* b0 = (const float*)d_in[7];
    const float* W1 = (const float*)d_in[8];
    const float* b1 = (const float*)d_in[9];
    const float* W2 = (const float*)d_in[10];
    const float* b2 = (const float*)d_in[11];
    const float* Wq = (const float*)d_in[12];
    const float* bq = (const float*)d_in[13];
    const float* Wk = (const float*)d_in[14];
    const float* bk = (const float*)d_in[15];

    int R       = in_sizes[0];
    int n_times = in_sizes[0];
    int V       = in_sizes[2] / R;
    int B       = in_sizes[5];

    k_rows<<<(R * 32 + 255) / 256, 256>>>(times, time_ptr, M, R, V, n_times);
    k_compact<<<B, 256>>>(X, R, V, B);
    k_mlp<<<B * 64 + 1, 128>>>(W0, b0, W1, b1, W2, b2, Wk, bk, Wq, bq, B);
    dim3 gs(B, NCHUNK);
    k_score<<<gs, 256>>>();
    k_expsum<<<B * 4, 256>>>();
    k_wsum<<<gs, 512>>>();
    k_final<<<B, 512>>>((float*)d_out);
}

// round 9
// speedup vs baseline: 1.0689x; 1.0689x over previous
#include <cuda_runtime.h>
#include <math.h>

// ---------------------------------------------------------------------------
// SeFT network, round 8:
//  - gather: coalesced ballot compaction (k_rows + k_compact)
//  - k_mlp: R5 dense128 (smem-staged weights, NO register pipeline - that
//    regressed via register pressure), f32x2 FFMA
//  - attention: flash-style two-pass
//      k_attnA (B x 8 blocks, 512 thr): scores + chunk-local softmax +
//        partial weighted enc sum (kT and enc each read once, no score
//        round-trips through DRAM)
//      k_attnB (B blocks): rescale-combine partials
// ---------------------------------------------------------------------------

#define BMAX    32
#define LSTRIDE 2048
#define NCHUNK  8           // LSTRIDE / 256
#define HID     128
#define NIN     34
#define ASTR    36          // activation row stride (floats)

typedef unsigned long long ull;

__device__ float    g_St[BMAX * LSTRIDE];
__device__ float    g_Sc[BMAX * LSTRIDE];
__device__ float    g_Sx[BMAX * LSTRIDE];
__device__ int      g_lens[BMAX];
__device__ int      g_maxlen;
__device__ int      g_rowcnt[4096];
__device__ unsigned g_rowmask[4096];
__device__ float    g_rowtime[4096];
__device__ float    g_enc[(size_t)BMAX * LSTRIDE * HID];   // [b][l][e]
__device__ float    g_kT [(size_t)BMAX * HID * LSTRIDE];   // [b][e][l]
__device__ float    g_q  [BMAX * HID];
__device__ float    g_cm  [BMAX * 4 * NCHUNK];             // chunk max
__device__ float    g_csum[BMAX * 4 * NCHUNK];             // chunk expsum
__device__ float    g_part[(size_t)BMAX * NCHUNK * 512];   // [b][chunk][h*128+e]

// ---- packed fp32x2 helpers -------------------------------------------------
__device__ __forceinline__ ull pack2(float x, float y) {
    ull r;
    asm("mov.b64 %0, {%1, %2};" : "=l"(r) : "f"(x), "f"(y));
    return r;
}
__device__ __forceinline__ void unpack2(ull v, float& lo, float& hi) {
    asm("mov.b64 {%0, %1}, %2;" : "=f"(lo), "=f"(hi) : "l"(v));
}
__device__ __forceinline__ ull ffma2(ull a, ull b, ull c) {
    ull d;
    asm("fma.rn.f32x2 %0, %1, %2, %3;" : "=l"(d) : "l"(a), "l"(b), "l"(c));
    return d;
}

// ---------------------------------------------------------------------------
// Kernel 1: per-row nonzero mask/count/time. One warp per row, coalesced.
// ---------------------------------------------------------------------------
__global__ void k_rows(const float* __restrict__ times,
                       const int*   __restrict__ time_ptr,
                       const int*   __restrict__ M,
                       int R, int V, int n_times)
{
    int w = (blockIdx.x * blockDim.x + threadIdx.x) >> 5;
    int lane = threadIdx.x & 31;
    if (w >= R) return;
    int m = 0;
    if (lane < V) m = (M[w * V + lane] != 0);
    unsigned mask = __ballot_sync(0xffffffffu, m);
    if (lane == 0) {
        g_rowmask[w] = mask;
        g_rowcnt[w]  = __popc(mask);
        int lo = 0, hi = n_times - 1;
        while (lo < hi) {
            int mid = (lo + hi + 1) >> 1;
            if (time_ptr[mid] <= w) lo = mid; else hi = mid - 1;
        }
        g_rowtime[w] = times[lo];
    }
}

// ---------------------------------------------------------------------------
// Kernel 2: per-patient compaction (rows contiguous per patient).
// ---------------------------------------------------------------------------
__global__ void k_compact(const float* __restrict__ X, int R, int V, int B)
{
    int b = blockIdx.x;
    int rpp = R / B;
    int r0 = b * rpp;
    int t = threadIdx.x;

    __shared__ int ssum[256];
    __shared__ int sstart[256];
    int cnt = (t < rpp) ? g_rowcnt[r0 + t] : 0;
    ssum[t] = cnt;
    __syncthreads();
    for (int off = 1; off < 256; off <<= 1) {
        int v = (t >= off) ? ssum[t - off] : 0;
        __syncthreads();
        ssum[t] += v;
        __syncthreads();
    }
    int tot = ssum[255];
    sstart[t] = ssum[t] - cnt;
    __syncthreads();

    int lane = t & 31, w = t >> 5;
    for (int lr = w; lr < rpp; lr += 8) {
        int r = r0 + lr;
        unsigned mask = g_rowmask[r];
        float tv = g_rowtime[r];
        int start = sstart[lr];
        if (lane < V && ((mask >> lane) & 1u)) {
            int pos = start + __popc(mask & ((1u << lane) - 1u));
            if (pos < LSTRIDE) {
                g_St[b * LSTRIDE + pos] = tv;
                g_Sc[b * LSTRIDE + pos] = (float)lane;
                g_Sx[b * LSTRIDE + pos] = X[r * V + lane];
            }
        }
    }
    if (t == 0) {
        int L = min(tot, LSTRIDE);
        g_lens[b] = L;
        atomicMax(&g_maxlen, L);   // idempotent across replays
    }
}

// ---------------------------------------------------------------------------
// 128->128 dense layer, f32x2, weights staged in smem chunks of 32 k-rows
// (R5 version - no register prefetch pipeline).
// Thread (r = t&63, h = t>>6) computes output rows r, r+64 over 16 obs.
// wbuf layout wbuf[kk*129 + o]: conflict-free STS and LDS.
// ---------------------------------------------------------------------------
__device__ __forceinline__ void dense128(const float* __restrict__ W,
                                         const float* __restrict__ bias,
                                         const float* sIn, float* wbuf,
                                         ull accA[8], ull accB[8],
                                         int r, int h, int tid)
{
    float bA = __ldg(&bias[r]);
    float bB = __ldg(&bias[r + 64]);
    ull iA = pack2(bA, bA), iB = pack2(bB, bB);
#pragma unroll
    for (int j = 0; j < 8; j++) { accA[j] = iA; accB[j] = iB; }

    for (int c = 0; c < 4; c++) {
        // stage 128x32 chunk, coalesced LDG.128, conflict-free STS
        for (int i4 = tid; i4 < 1024; i4 += 128) {
            int e  = i4 << 2;        // element index within chunk = o*32 + kk
            int o  = e >> 5;
            int kk = e & 31;
            float4 v = __ldg((const float4*)(W + o * HID + c * 32 + kk));
            wbuf[kk * 129 + o]       = v.x;
            wbuf[(kk + 1) * 129 + o] = v.y;
            wbuf[(kk + 2) * 129 + o] = v.z;
            wbuf[(kk + 3) * 129 + o] = v.w;
        }
        __syncthreads();
#pragma unroll 4
        for (int kk = 0; kk < 32; kk++) {
            float wA = wbuf[kk * 129 + r];
            float wB = wbuf[kk * 129 + 64 + r];
            ull wA2 = pack2(wA, wA), wB2 = pack2(wB, wB);
            const ulonglong2* row =
                (const ulonglong2*)(sIn + (c * 32 + kk) * ASTR + h * 16);
#pragma unroll
            for (int p = 0; p < 4; p++) {
                ulonglong2 v = row[p];
                accA[2 * p]     = ffma2(v.x, wA2, accA[2 * p]);
                accA[2 * p + 1] = ffma2(v.y, wA2, accA[2 * p + 1]);
                accB[2 * p]     = ffma2(v.x, wB2, accB[2 * p]);
                accB[2 * p + 1] = ffma2(v.y, wB2, accB[2 * p + 1]);
            }
        }
        __syncthreads();
    }
}

// relu epilogue into [k][obs] smem for rows r, r+64, obs half h
__device__ __forceinline__ void epi_relu(float* dst, ull accA[8], ull accB[8],
                                         int r, int h)
{
    float* dA = dst + r * ASTR + h * 16;
    float* dB = dst + (r + 64) * ASTR + h * 16;
#pragma unroll
    for (int j = 0; j < 8; j++) {
        float lo, hi;
        unpack2(accA[j], lo, hi);
        *(ull*)(dA + 2 * j) = pack2(fmaxf(lo, 0.f), fmaxf(hi, 0.f));
        unpack2(accB[j], lo, hi);
        *(ull*)(dB + 2 * j) = pack2(fmaxf(lo, 0.f), fmaxf(hi, 0.f));
    }
}

// ---------------------------------------------------------------------------
// Kernel 3: fused MLP + projection, 32-obs tiles.
// Block 0 = query path (lastfeat inline, Wq -> g_q). Others: enc + kT.
//   L0: in sf, w sA, out sA      L1: in sA, w sB, out sB
//   L2: in sB, w sA, out sA+enc  Pr: in sA, w sB, out global
// ---------------------------------------------------------------------------
__global__ __launch_bounds__(128) void k_mlp(
    const float* __restrict__ W0, const float* __restrict__ b0,
    const float* __restrict__ W1, const float* __restrict__ b1,
    const float* __restrict__ W2, const float* __restrict__ b2,
    const float* __restrict__ Wk, const float* __restrict__ bk,
    const float* __restrict__ Wq, const float* __restrict__ bq,
    int B)
{
    __shared__ __align__(16) float sf[NIN * ASTR];
    __shared__ __align__(16) float sA[HID * ASTR];
    __shared__ __align__(16) float sB[HID * ASTR];

    int tid = threadIdx.x;
    int r = tid & 63;
    int h = tid >> 6;

    bool special = (blockIdx.x == 0);
    int b = 0, l0 = 0, nv = 0;
    if (!special) {
        int bi = blockIdx.x - 1;
        b = bi >> 6;
        int lt = bi & 63;
        int len = g_lens[b];
        l0 = lt * 32;
        if (l0 >= len) return;
        nv = min(32, len - l0);
    } else {
        nv = min(B, 32);
    }

    // stage W0 [128][34] into sA at stride 129 (dead until L0 epilogue)
    for (int i = tid; i < HID * NIN; i += 128) {
        int o = i / NIN, k = i - o * NIN;
        sA[k * 129 + o] = __ldg(&W0[i]);
    }

    // features into [k][obs] layout
    if (tid < 32) {
        int o = tid;
        float tv = 0.f, cv = 0.f, xv = 0.f;
        if (special) {
            int L = g_maxlen;
            if (o < nv && L >= 1 && g_lens[o] == L) {
                tv = g_St[o * LSTRIDE + L - 1];
                cv = g_Sc[o * LSTRIDE + L - 1];
                xv = g_Sx[o * LSTRIDE + L - 1];
            }
        } else if (o < nv) {
            tv = g_St[b * LSTRIDE + l0 + o];
            cv = g_Sc[b * LSTRIDE + l0 + o];
            xv = g_Sx[b * LSTRIDE + l0 + o];
        }
#pragma unroll
        for (int i = 0; i < 16; i++) {
            float ts = powf(100.0f, (float)i * (1.0f / 15.0f));
            float sn, cs;
            sincosf(tv / ts, &sn, &cs);
            sf[i * ASTR + o]        = sn;
            sf[(16 + i) * ASTR + o] = cs;
        }
        sf[32 * ASTR + o] = cv;
        sf[33 * ASTR + o] = xv;
    }
    __syncthreads();

    ull accA[8], accB[8];

    // ---- layer 0: 34 -> 128, relu (weights in sA, input sf) ----
    {
        float bA = __ldg(&b0[r]);
        float bB = __ldg(&b0[r + 64]);
        ull iA = pack2(bA, bA), iB = pack2(bB, bB);
#pragma unroll
        for (int j = 0; j < 8; j++) { accA[j] = iA; accB[j] = iB; }
#pragma unroll 2
        for (int k = 0; k < NIN; k++) {
            float wA = sA[k * 129 + r];
            float wB = sA[k * 129 + 64 + r];
            ull wA2 = pack2(wA, wA), wB2 = pack2(wB, wB);
            const ulonglong2* row = (const ulonglong2*)(sf + k * ASTR + h * 16);
#pragma unroll
            for (int p = 0; p < 4; p++) {
                ulonglong2 v = row[p];
                accA[2 * p]     = ffma2(v.x, wA2, accA[2 * p]);
                accA[2 * p + 1] = ffma2(v.y, wA2, accA[2 * p + 1]);
                accB[2 * p]     = ffma2(v.x, wB2, accB[2 * p]);
                accB[2 * p + 1] = ffma2(v.y, wB2, accB[2 * p + 1]);
            }
        }
        __syncthreads();            // weights in sA dead after this
        epi_relu(sA, accA, accB, r, h);
    }
    __syncthreads();

    // ---- layer 1: 128 -> 128, relu (in sA, weights+out sB) ----
    dense128(W1, b1, sA, sB, accA, accB, r, h, tid);
    epi_relu(sB, accA, accB, r, h);
    __syncthreads();

    // ---- layer 2 (enc): 128 -> 128, linear (in sB, weights+out sA) ----
    dense128(W2, b2, sB, sA, accA, accB, r, h, tid);
    {
        float vA[16], vB[16];
#pragma unroll
        for (int j = 0; j < 8; j++) {
            unpack2(accA[j], vA[2 * j], vA[2 * j + 1]);
            unpack2(accB[j], vB[2 * j], vB[2 * j + 1]);
        }
        float* dA = sA + r * ASTR + h * 16;
        float* dB = sA + (r + 64) * ASTR + h * 16;
#pragma unroll
        for (int j = 0; j < 8; j++) {
            *(ull*)(dA + 2 * j) = accA[j];
            *(ull*)(dB + 2 * j) = accB[j];
        }
        if (!special) {
#pragma unroll
            for (int o = 0; o < 16; o++) {
                int og = h * 16 + o;
                if (og < nv) {
                    size_t base = ((size_t)b * LSTRIDE + l0 + og) * HID;
                    g_enc[base + r]      = vA[o];
                    g_enc[base + 64 + r] = vB[o];
                }
            }
        }
    }
    __syncthreads();

    // ---- projection: Wk (normal) or Wq (special); in sA, weights sB ----
    dense128(special ? Wq : Wk, special ? bq : bk, sA, sB, accA, accB, r, h, tid);
    {
        float vA[16], vB[16];
#pragma unroll
        for (int j = 0; j < 8; j++) {
            unpack2(accA[j], vA[2 * j], vA[2 * j + 1]);
            unpack2(accB[j], vB[2 * j], vB[2 * j + 1]);
        }
        if (special) {
#pragma unroll
            for (int o = 0; o < 16; o++) {
                int og = h * 16 + o;
                if (og < nv) {
                    g_q[og * HID + r]      = vA[o];
                    g_q[og * HID + 64 + r] = vB[o];
                }
            }
        } else {
            float* gkA = g_kT + ((size_t)b * HID + r) * LSTRIDE + l0 + h * 16;
            float* gkB = g_kT + ((size_t)b * HID + 64 + r) * LSTRIDE + l0 + h * 16;
#pragma unroll
            for (int o = 0; o < 16; o += 4) {
                int og = h * 16 + o;
                if (og + 4 <= nv) {
                    *(float4*)(gkA + o) = make_float4(vA[o], vA[o+1], vA[o+2], vA[o+3]);
                    *(float4*)(gkB + o) = make_float4(vB[o], vB[o+1], vB[o+2], vB[o+3]);
                } else {
                    for (int m = 0; m < 4; m++)
                        if (og + m < nv) { gkA[o + m] = vA[o + m]; gkB[o + m] = vB[o + m]; }
                }
            }
        }
    }
}

// ---------------------------------------------------------------------------
// Kernel 4: flash-style attention pass A. grid (B, NCHUNK), 512 threads.
// Per (b, chunk): scores (coalesced over l from kT), chunk-local max/exp/sum
// in smem, partial weighted enc sum with chunk-local weights.
// Outputs: g_part[b][chunk][h*128+e], g_cm/g_csum per (b,h,chunk).
// ---------------------------------------------------------------------------
__global__ __launch_bounds__(512) void k_attnA()
{
    int b     = blockIdx.x;
    int chunk = blockIdx.y;
    int t     = threadIdx.x;
    int len   = min(g_lens[b], LSTRIDE);
    int l0    = chunk * 256;

    __shared__ float sq[HID];
    __shared__ float ssc[4 * 256];
    __shared__ float sred[512];
    __shared__ float sm[4], ssum[4];

    if (t < HID) sq[t] = g_q[b * HID + t];
    __syncthreads();

    const float scale = 0.17677669529663687f; // 1/sqrt(32)

    // scores: thread (li = t&255, head pair hp = (t>>8)*2)
    {
        int li = t & 255;
        int hp = (t >> 8) << 1;
        int l  = l0 + li;
        float s0 = -1e30f, s1 = -1e30f;
        if (l < len) {
            const float* kb = g_kT + (size_t)b * HID * LSTRIDE + l;
            float a0 = 0.f, a1 = 0.f;
#pragma unroll 8
            for (int e2 = 0; e2 < 32; e2++) {
                a0 = fmaf(__ldg(&kb[(size_t)(hp * 32 + e2) * LSTRIDE]),
                          sq[hp * 32 + e2], a0);
                a1 = fmaf(__ldg(&kb[(size_t)((hp + 1) * 32 + e2) * LSTRIDE]),
                          sq[(hp + 1) * 32 + e2], a1);
            }
            s0 = a0 * scale;
            s1 = a1 * scale;
        }
        ssc[hp * 256 + li]       = s0;
        ssc[(hp + 1) * 256 + li] = s1;
    }
    __syncthreads();

    int h = t >> 7, i = t & 127;

    // chunk max per head
    sred[t] = fmaxf(ssc[h * 256 + i], ssc[h * 256 + 128 + i]);
    __syncthreads();
    for (int s = 64; s > 0; s >>= 1) {
        if (i < s) sred[t] = fmaxf(sred[t], sred[t + s]);
        __syncthreads();
    }
    if (i == 0) sm[h] = sred[t];
    __syncthreads();

    // exp weights (zero for padded l)
#pragma unroll
    for (int j = 0; j < 2; j++) {
        int idx = t + j * 512;
        int hh = idx >> 8, li = idx & 255;
        float wv = 0.f;
        if (l0 + li < len) wv = expf(ssc[idx] - sm[hh]);
        ssc[idx] = wv;
    }
    __syncthreads();

    // chunk expsum per head
    sred[t] = ssc[h * 256 + i] + ssc[h * 256 + 128 + i];
    __syncthreads();
    for (int s = 64; s > 0; s >>= 1) {
        if (i < s) sred[t] += sred[t + s];
        __syncthreads();
    }
    if (i == 0) ssum[h] = sred[t];

    // partial weighted enc sum: thread (h, e = i)
    int nl = max(0, min(256, len - l0));
    const float* encb = g_enc + ((size_t)b * LSTRIDE + l0) * HID + i;
    const float* wh = ssc + h * 256;
    float a0 = 0.f, a1 = 0.f, a2 = 0.f, a3 = 0.f;
    int l = 0;
    for (; l + 3 < nl; l += 4) {
        a0 = fmaf(wh[l],     __ldg(&encb[(size_t)l * HID]),       a0);
        a1 = fmaf(wh[l + 1], __ldg(&encb[(size_t)(l + 1) * HID]), a1);
        a2 = fmaf(wh[l + 2], __ldg(&encb[(size_t)(l + 2) * HID]), a2);
        a3 = fmaf(wh[l + 3], __ldg(&encb[(size_t)(l + 3) * HID]), a3);
    }
    for (; l < nl; l++) a0 = fmaf(wh[l], __ldg(&encb[(size_t)l * HID]), a0);
    g_part[((size_t)b * NCHUNK + chunk) * 512 + t] = (a0 + a1) + (a2 + a3);

    if (i == 0) {
        g_cm  [(b * 4 + h) * NCHUNK + chunk] = sm[h];
        g_csum[(b * 4 + h) * NCHUNK + chunk] = ssum[h];
    }
}

// ---------------------------------------------------------------------------
// Kernel 5: rescale-combine. grid B, 512 threads, thread = (h = t>>7, e).
// out = sum_c part_c * exp(m_c - m) / sum_c sum_c * exp(m_c - m)
// ---------------------------------------------------------------------------
__global__ __launch_bounds__(512) void k_attnB(float* __restrict__ out)
{
    int b = blockIdx.x;
    int t = threadIdx.x;
    int h = t >> 7;
    int bh = b * 4 + h;

    float m = -1e30f;
#pragma unroll
    for (int c = 0; c < NCHUNK; c++) m = fmaxf(m, g_cm[bh * NCHUNK + c]);

    float denom = 0.f, num = 0.f;
#pragma unroll
    for (int c = 0; c < NCHUNK; c++) {
        float f = expf(g_cm[bh * NCHUNK + c] - m);
        denom = fmaf(g_csum[bh * NCHUNK + c], f, denom);
        num   = fmaf(g_part[((size_t)b * NCHUNK + c) * 512 + t], f, num);
    }
    out[b * 512 + t] = num / denom;
}

// ---------------------------------------------------------------------------
extern "C" void kernel_launch(void* const* d_in, const int* in_sizes, int n_in,
                              void* d_out, int out_size)
{
    const float* times    = (const float*)d_in[0];
    const int*   time_ptr = (const int*)  d_in[1];
    const float* X        = (const float*)d_in[2];
    const int*   M        = (const int*)  d_in[3];
    const float* W0 = (const float*)d_in[6];
    const float* b0 = (const float*)d_in[7];
    const float* W1 = (const float*)d_in[8];
    const float* b1 = (const float*)d_in[9];
    const float* W2 = (const float*)d_in[10];
    const float* b2 = (const float*)d_in[11];
    const float* Wq = (const float*)d_in[12];
    const float* bq = (const float*)d_in[13];
    const float* Wk = (const float*)d_in[14];
    const float* bk = (const float*)d_in[15];

    int R       = in_sizes[0];
    int n_times = in_sizes[0];
    int V       = in_sizes[2] / R;
    int B       = in_sizes[5];

    k_rows<<<(R * 32 + 255) / 256, 256>>>(times, time_ptr, M, R, V, n_times);
    k_compact<<<B, 256>>>(X, R, V, B);
    k_mlp<<<B * 64 + 1, 128>>>(W0, b0, W1, b1, W2, b2, Wk, bk, Wq, bq, B);
    dim3 gs(B, NCHUNK);
    k_attnA<<<gs, 512>>>();
    k_attnB<<<B, 512>>>((float*)d_out);
}